// round 15
// baseline (speedup 1.0000x reference)
#include <cuda_runtime.h>
#include <cstdint>

#define Npts 100000
#define Mpts 100000
#define NNB 32
#define KP 15
#define FD 64
#define CD 64

constexpr int MT = 64;             // output points per block
constexpr int THREADS = 256;
constexpr int GRID = (Mpts + MT - 1) / MT;   // 1563

constexpr int TSTR_F = 68;         // tile row stride in floats (272B; conflict-free ldmatrix)
constexpr int TSTR_B = 272;
constexpr int ATILE_BYTES = 64 * TSTR_B;     // 17408

// ---- shared memory byte offsets (R8 layout: 3 CTAs/SM) ----
constexpr int A_T0 = 0;            // [64 m][68] f32 (buffer 0) = 17408
constexpr int A_T1 = 17408;        // buffer 1
constexpr int S_PQ = 34816;        // [64][32] float4 (dx,dy,dz, idx-bits) = 32768
constexpr int S_KM = 67584;        // [64][16] u32 masks = 4096
constexpr int S_KP = 71680;        // [15][4] f32 = 256
constexpr int SMEM_TOTAL = 71936;

// B fragments in mma register layout: [k][wcHalf(2)][ks(8)][nt2(2)][lane(32)] uint4
__device__ __align__(16) uint4 g_Bfrag[KP * 2 * 8 * 2 * 32];

__device__ __forceinline__ uint32_t smem_u32(const void* p) {
    uint32_t a;
    asm("{ .reg .u64 t; cvta.to.shared.u64 t, %1; cvt.u32.u64 %0, t; }" : "=r"(a) : "l"(p));
    return a;
}

__device__ __forceinline__ void ldmx4(uint32_t* r, uint32_t addr) {
    asm volatile("ldmatrix.sync.aligned.m8n8.x4.shared.b16 {%0,%1,%2,%3}, [%4];"
                 : "=r"(r[0]), "=r"(r[1]), "=r"(r[2]), "=r"(r[3]) : "r"(addr));
}

__device__ __forceinline__ void mma1688(float* d, const uint32_t* a, uint32_t b0, uint32_t b1) {
    asm volatile(
        "mma.sync.aligned.m16n8k8.row.col.f32.tf32.tf32.f32 "
        "{%0,%1,%2,%3}, {%4,%5,%6,%7}, {%8,%9}, {%0,%1,%2,%3};"
        : "+f"(d[0]), "+f"(d[1]), "+f"(d[2]), "+f"(d[3])
        : "r"(a[0]), "r"(a[1]), "r"(a[2]), "r"(a[3]), "r"(b0), "r"(b1));
}

__device__ __forceinline__ uint32_t tf32r(float x) {
    uint32_t u;
    asm("cvt.rna.tf32.f32 %0, %1;" : "=r"(u) : "f"(x));
    return u;
}

// ------------- prologue: build B fragments in exact mma register layout -------------
__global__ void bfrag_prep(const float* __restrict__ kv) {
    __shared__ __align__(16) uint32_t tile[64 * TSTR_F];
    const int k   = blockIdx.x;
    const int tid = threadIdx.x;
    const int wid = tid >> 5;
    const int ln  = tid & 31;

    for (int j = 0; j < 64; ++j) {
        const int f = j, c = tid;
        tile[c * TSTR_F + f] = tf32r(kv[((size_t)k * 64 + f) * 64 + c]);
    }
    __syncthreads();

    const int wc = wid * 32;
    const uint32_t base = smem_u32(tile) +
        (uint32_t)((wc + (ln & 7) + ((ln >> 4) & 1) * 8) * TSTR_B + ((ln >> 3) & 1) * 16);
    #pragma unroll
    for (int ks = 0; ks < 8; ++ks) {
        #pragma unroll
        for (int nt2 = 0; nt2 < 2; ++nt2) {
            uint32_t b[4];
            ldmx4(b, base + nt2 * (16 * TSTR_B) + ks * 32);
            g_Bfrag[(((k * 2 + wid) * 8 + ks) * 2 + nt2) * 32 + ln] =
                make_uint4(b[0], b[1], b[2], b[3]);
        }
    }
}

// ------------------------------- main kernel -------------------------------
__global__ void __launch_bounds__(THREADS, 3)
kpconv_mma(const float* __restrict__ points,
           const float* __restrict__ features,
           const float* __restrict__ outpts,
           const int*   __restrict__ nbr,
           const float* __restrict__ kpts,
           float*       __restrict__ out)
{
    extern __shared__ char smem[];
    const uint32_t smem_base = smem_u32(smem);
    float*    s_kp = reinterpret_cast<float*>(smem + S_KP);
    unsigned* s_km = reinterpret_cast<unsigned*>(smem + S_KM);
    float4*   s_pq = reinterpret_cast<float4*>(smem + S_PQ);

    const int tid = threadIdx.x;
    const int wid = tid >> 5;
    const int ln  = tid & 31;
    const int m0  = blockIdx.x * MT;

    if (tid < KP * 3) s_kp[(tid / 3) * 4 + (tid % 3)] = kpts[tid];
    __syncthreads();

    // ---- setup: pq vectors + per-(m,k) neighbor bitmasks ----
    #pragma unroll 1
    for (int j = 0; j < (MT * NNB) / THREADS; ++j) {
        const int i = j * THREADS + tid;
        const int m = i >> 5;                 // constant within a warp
        const int gm = m0 + m;
        float dx, dy, dz;
        int gi = 0;
        if (gm < Mpts) {
            gi = nbr[(size_t)gm * NNB + ln];
            const float qx = outpts[gm * 3 + 0];
            const float qy = outpts[gm * 3 + 1];
            const float qz = outpts[gm * 3 + 2];
            dx = __ldg(points + 3 * (size_t)gi + 0) - qx;
            dy = __ldg(points + 3 * (size_t)gi + 1) - qy;
            dz = __ldg(points + 3 * (size_t)gi + 2) - qz;
        } else {
            dx = dy = dz = 1e18f;
        }
        s_pq[i] = make_float4(dx, dy, dz, __int_as_float(gi));
        #pragma unroll
        for (int k = 0; k < KP; ++k) {
            const float ex = dx - s_kp[k * 4 + 0];
            const float ey = dy - s_kp[k * 4 + 1];
            const float ez = dz - s_kp[k * 4 + 2];
            const float d2 = ex * ex + ey * ey + ez * ez;
            const unsigned bal = __ballot_sync(0xffffffffu, d2 < 1.0f);
            if (ln == 0) s_km[m * 16 + k] = bal;
        }
    }

    // ---- per-thread mappings ----
    const int mgrp = tid >> 3;          // gather: 8 threads per m
    const int oct  = tid & 7;           // 16B chunk index: oct and oct+8

    const int wm = (wid & 3) * 16;      // mma warp tile: rows
    const int wc = (wid >> 2) * 32;     // mma warp tile: cols
    const uint32_t aaddr = smem_base + A_T0 +
        (uint32_t)((wm + (ln & 7) + ((ln >> 3) & 1) * 8) * TSTR_B + ((ln >> 4) & 1) * 16);
    const uint4* bwarp = g_Bfrag + ((wid >> 2) * 8 * 2) * 32 + ln;

    const float4* pqm0 = s_pq + mgrp * 32;
    const float4* pqm1 = s_pq + (32 + mgrp) * 32;

    float Dacc[4][4];
    #pragma unroll
    for (int a = 0; a < 4; ++a)
        #pragma unroll
        for (int b = 0; b < 4; ++b) Dacc[a][b] = 0.f;

    __syncthreads();   // masks + pq visible

    #pragma unroll 1
    for (int k = 0; k < KP; ++k) {
        const float kpx = s_kp[k * 4 + 0];
        const float kpy = s_kp[k * 4 + 1];
        const float kpz = s_kp[k * 4 + 2];

        float acc[2][8];
        #pragma unroll
        for (int p = 0; p < 2; ++p)
            #pragma unroll
            for (int i = 0; i < 8; ++i) acc[p][i] = 0.f;

        // ---------- merged first wave: 2 entries from EACH m, 16 LDG.128 in flight ----------
        unsigned mk0 = s_km[mgrp * 16 + k];
        unsigned mk1 = s_km[(32 + mgrp) * 16 + k];
        {
            int n00 = 0, n01 = 0, n10 = 0, n11 = 0;
            const bool h00 = (mk0 != 0);
            if (h00) { n00 = __ffs(mk0) - 1; mk0 &= mk0 - 1; }
            const bool h01 = (mk0 != 0);
            if (h01) { n01 = __ffs(mk0) - 1; mk0 &= mk0 - 1; }
            const bool h10 = (mk1 != 0);
            if (h10) { n10 = __ffs(mk1) - 1; mk1 &= mk1 - 1; }
            const bool h11 = (mk1 != 0);
            if (h11) { n11 = __ffs(mk1) - 1; mk1 &= mk1 - 1; }

            const float4 pq00 = pqm0[n00];
            const float4 pq01 = pqm0[n01];
            const float4 pq10 = pqm1[n10];
            const float4 pq11 = pqm1[n11];

            const float4* f00 = reinterpret_cast<const float4*>(
                features + (size_t)__float_as_int(pq00.w) * FD);
            const float4* f01 = reinterpret_cast<const float4*>(
                features + (size_t)__float_as_int(pq01.w) * FD);
            const float4* f10 = reinterpret_cast<const float4*>(
                features + (size_t)__float_as_int(pq10.w) * FD);
            const float4* f11 = reinterpret_cast<const float4*>(
                features + (size_t)__float_as_int(pq11.w) * FD);

            const float4 A00 = __ldg(f00 + oct), B00 = __ldg(f00 + oct + 8);
            const float4 A01 = __ldg(f01 + oct), B01 = __ldg(f01 + oct + 8);
            const float4 A10 = __ldg(f10 + oct), B10 = __ldg(f10 + oct + 8);
            const float4 A11 = __ldg(f11 + oct), B11 = __ldg(f11 + oct + 8);

            // weights overlap the loads' latency
            float e0, e1, e2;
            e0 = pq00.x - kpx; e1 = pq00.y - kpy; e2 = pq00.z - kpz;
            const float w00 = h00 ? 1.0f - __fsqrt_rn(e0 * e0 + e1 * e1 + e2 * e2) : 0.0f;
            e0 = pq01.x - kpx; e1 = pq01.y - kpy; e2 = pq01.z - kpz;
            const float w01 = h01 ? 1.0f - __fsqrt_rn(e0 * e0 + e1 * e1 + e2 * e2) : 0.0f;
            e0 = pq10.x - kpx; e1 = pq10.y - kpy; e2 = pq10.z - kpz;
            const float w10 = h10 ? 1.0f - __fsqrt_rn(e0 * e0 + e1 * e1 + e2 * e2) : 0.0f;
            e0 = pq11.x - kpx; e1 = pq11.y - kpy; e2 = pq11.z - kpz;
            const float w11 = h11 ? 1.0f - __fsqrt_rn(e0 * e0 + e1 * e1 + e2 * e2) : 0.0f;

            acc[0][0] += w00 * A00.x + w01 * A01.x;
            acc[0][1] += w00 * A00.y + w01 * A01.y;
            acc[0][2] += w00 * A00.z + w01 * A01.z;
            acc[0][3] += w00 * A00.w + w01 * A01.w;
            acc[0][4] += w00 * B00.x + w01 * B01.x;
            acc[0][5] += w00 * B00.y + w01 * B01.y;
            acc[0][6] += w00 * B00.z + w01 * B01.z;
            acc[0][7] += w00 * B00.w + w01 * B01.w;
            acc[1][0] += w10 * A10.x + w11 * A11.x;
            acc[1][1] += w10 * A10.y + w11 * A11.y;
            acc[1][2] += w10 * A10.z + w11 * A11.z;
            acc[1][3] += w10 * A10.w + w11 * A11.w;
            acc[1][4] += w10 * B10.x + w11 * B11.x;
            acc[1][5] += w10 * B10.y + w11 * B11.y;
            acc[1][6] += w10 * B10.z + w11 * B11.z;
            acc[1][7] += w10 * B10.w + w11 * B11.w;
        }

        // ---------- tails (P ~ 0.6, avg ~1 entry-pair) ----------
        #pragma unroll
        for (int p = 0; p < 2; ++p) {
            unsigned mask = (p == 0) ? mk0 : mk1;
            const float4* pqm = (p == 0) ? pqm0 : pqm1;
            while (mask) {
                const int n0 = __ffs(mask) - 1;
                mask &= mask - 1;
                const bool has1 = (mask != 0);
                int n1 = n0;
                if (has1) { n1 = __ffs(mask) - 1; mask &= mask - 1; }

                const float4 pq0 = pqm[n0];
                const float4 pq1 = pqm[n1];

                const float4* fp0 = reinterpret_cast<const float4*>(
                    features + (size_t)__float_as_int(pq0.w) * FD);
                const float4* fp1 = reinterpret_cast<const float4*>(
                    features + (size_t)__float_as_int(pq1.w) * FD);
                const float4 a0 = __ldg(fp0 + oct);
                const float4 b0 = __ldg(fp0 + oct + 8);
                const float4 a1 = __ldg(fp1 + oct);
                const float4 b1 = __ldg(fp1 + oct + 8);

                const float ex0 = pq0.x - kpx, ey0 = pq0.y - kpy, ez0 = pq0.z - kpz;
                const float w0 = 1.0f - __fsqrt_rn(ex0 * ex0 + ey0 * ey0 + ez0 * ez0);
                float w1 = 0.0f;
                if (has1) {
                    const float ex1 = pq1.x - kpx, ey1 = pq1.y - kpy, ez1 = pq1.z - kpz;
                    w1 = 1.0f - __fsqrt_rn(ex1 * ex1 + ey1 * ey1 + ez1 * ez1);
                }
                acc[p][0] += w0 * a0.x + w1 * a1.x;
                acc[p][1] += w0 * a0.y + w1 * a1.y;
                acc[p][2] += w0 * a0.z + w1 * a1.z;
                acc[p][3] += w0 * a0.w + w1 * a1.w;
                acc[p][4] += w0 * b0.x + w1 * b1.x;
                acc[p][5] += w0 * b0.y + w1 * b1.y;
                acc[p][6] += w0 * b0.z + w1 * b1.z;
                acc[p][7] += w0 * b0.w + w1 * b1.w;
            }
        }

        // ---------- tf32-round + STS A tile into parity buffer ----------
        const uint32_t abase = (uint32_t)((k & 1) * ATILE_BYTES);
        #pragma unroll
        for (int p = 0; p < 2; ++p) {
            const int m = p * 32 + mgrp;
            uint32_t t[8];
            #pragma unroll
            for (int i = 0; i < 8; ++i) t[i] = tf32r(acc[p][i]);
            const uint32_t base = abase + (uint32_t)(m * TSTR_B + oct * 16);
            *reinterpret_cast<uint4*>(smem + base)       = make_uint4(t[0], t[1], t[2], t[3]);
            *reinterpret_cast<uint4*>(smem + base + 128) = make_uint4(t[4], t[5], t[6], t[7]);
        }
        __syncthreads();   // A(k) visible; MMA(k-1) ldmatrix already issued by all warps

        // ---------- mma: D += A · B  (tf32; B operands via coalesced LDG) ----------
        const uint4* bk = bwarp + (size_t)k * (2 * 8 * 2 * 32);
        const uint32_t abuf = aaddr + abase;
        #pragma unroll
        for (int ks = 0; ks < 8; ++ks) {
            uint32_t a[4];
            ldmx4(a, abuf + ks * 32);
            #pragma unroll
            for (int nt2 = 0; nt2 < 2; ++nt2) {
                const uint4 bb = __ldg(bk + (ks * 2 + nt2) * 32);
                mma1688(Dacc[nt2 * 2 + 0], a, bb.x, bb.y);
                mma1688(Dacc[nt2 * 2 + 1], a, bb.z, bb.w);
            }
        }
    }

    // ---------- epilogue ----------
    const int gid = ln >> 2, tg = ln & 3;
    const int r0 = m0 + wm + gid;
    const int r1 = r0 + 8;
    #pragma unroll
    for (int nt = 0; nt < 4; ++nt) {
        const int cc = wc + nt * 8 + tg * 2;
        if (r0 < Mpts)
            *reinterpret_cast<float2*>(out + (size_t)r0 * CD + cc) =
                make_float2(Dacc[nt][0], Dacc[nt][1]);
        if (r1 < Mpts)
            *reinterpret_cast<float2*>(out + (size_t)r1 * CD + cc) =
                make_float2(Dacc[nt][2], Dacc[nt][3]);
    }
}

extern "C" void kernel_launch(void* const* d_in, const int* in_sizes, int n_in,
                              void* d_out, int out_size)
{
    const float* points   = (const float*)d_in[0];
    const float* features = (const float*)d_in[1];
    const float* outpts   = (const float*)d_in[2];
    const int*   nbr      = (const int*)  d_in[3];
    const float* kpts     = (const float*)d_in[4];
    const float* kvals    = (const float*)d_in[5];

    bfrag_prep<<<KP, 64>>>(kvals);

    cudaFuncSetAttribute(kpconv_mma, cudaFuncAttributeMaxDynamicSharedMemorySize, SMEM_TOTAL);
    kpconv_mma<<<GRID, THREADS, SMEM_TOTAL>>>(points, features, outpts, nbr, kpts, (float*)d_out);
}

// round 16
// speedup vs baseline: 1.0701x; 1.0701x over previous
#include <cuda_runtime.h>
#include <cstdint>

#define Npts 100000
#define Mpts 100000
#define NNB 32
#define KP 15
#define FD 64
#define CD 64

constexpr int MT = 64;             // output points per block
constexpr int THREADS = 256;
constexpr int GRID = (Mpts + MT - 1) / MT;   // 1563

constexpr int TSTR_F = 68;         // tile row stride in floats (272B; conflict-free ldmatrix)
constexpr int TSTR_B = 272;
constexpr int ATILE_BYTES = 64 * TSTR_B;     // 17408

// ---- shared memory byte offsets (R8 layout: 3 CTAs/SM) ----
constexpr int A_T0 = 0;            // [64 m][68] f32 (buffer 0) = 17408
constexpr int A_T1 = 17408;        // buffer 1
constexpr int S_PQ = 34816;        // [64][32] float4 (dx,dy,dz, idx-bits) = 32768
constexpr int S_KM = 67584;        // [64][16] u32 masks = 4096
constexpr int S_KP = 71680;        // [15][4] f32 = 256
constexpr int SMEM_TOTAL = 71936;

// B fragments in mma register layout: [k][wcHalf(2)][ks(8)][nt2(2)][lane(32)] uint4
__device__ __align__(16) uint4 g_Bfrag[KP * 2 * 8 * 2 * 32];
// padded point coordinates: one aligned LDG.128 per neighbor in setup
__device__ __align__(16) float4 g_pts[Npts];

__device__ __forceinline__ uint32_t smem_u32(const void* p) {
    uint32_t a;
    asm("{ .reg .u64 t; cvta.to.shared.u64 t, %1; cvt.u32.u64 %0, t; }" : "=r"(a) : "l"(p));
    return a;
}

__device__ __forceinline__ void ldmx4(uint32_t* r, uint32_t addr) {
    asm volatile("ldmatrix.sync.aligned.m8n8.x4.shared.b16 {%0,%1,%2,%3}, [%4];"
                 : "=r"(r[0]), "=r"(r[1]), "=r"(r[2]), "=r"(r[3]) : "r"(addr));
}

__device__ __forceinline__ void mma1688(float* d, const uint32_t* a, uint32_t b0, uint32_t b1) {
    asm volatile(
        "mma.sync.aligned.m16n8k8.row.col.f32.tf32.tf32.f32 "
        "{%0,%1,%2,%3}, {%4,%5,%6,%7}, {%8,%9}, {%0,%1,%2,%3};"
        : "+f"(d[0]), "+f"(d[1]), "+f"(d[2]), "+f"(d[3])
        : "r"(a[0]), "r"(a[1]), "r"(a[2]), "r"(a[3]), "r"(b0), "r"(b1));
}

__device__ __forceinline__ uint32_t tf32r(float x) {
    uint32_t u;
    asm("cvt.rna.tf32.f32 %0, %1;" : "=r"(u) : "f"(x));
    return u;
}

// ------------- prologue 0: pad points [N,3] -> float4 [N] -------------
__global__ void pts_prep(const float* __restrict__ pts) {
    int i = blockIdx.x * blockDim.x + threadIdx.x;
    if (i < Npts)
        g_pts[i] = make_float4(pts[3 * i], pts[3 * i + 1], pts[3 * i + 2], 0.f);
}

// ------------- prologue 1: build B fragments in exact mma register layout -------------
__global__ void bfrag_prep(const float* __restrict__ kv) {
    __shared__ __align__(16) uint32_t tile[64 * TSTR_F];
    const int k   = blockIdx.x;
    const int tid = threadIdx.x;
    const int wid = tid >> 5;
    const int ln  = tid & 31;

    for (int j = 0; j < 64; ++j) {
        const int f = j, c = tid;
        tile[c * TSTR_F + f] = tf32r(kv[((size_t)k * 64 + f) * 64 + c]);
    }
    __syncthreads();

    const int wc = wid * 32;
    const uint32_t base = smem_u32(tile) +
        (uint32_t)((wc + (ln & 7) + ((ln >> 4) & 1) * 8) * TSTR_B + ((ln >> 3) & 1) * 16);
    #pragma unroll
    for (int ks = 0; ks < 8; ++ks) {
        #pragma unroll
        for (int nt2 = 0; nt2 < 2; ++nt2) {
            uint32_t b[4];
            ldmx4(b, base + nt2 * (16 * TSTR_B) + ks * 32);
            g_Bfrag[(((k * 2 + wid) * 8 + ks) * 2 + nt2) * 32 + ln] =
                make_uint4(b[0], b[1], b[2], b[3]);
        }
    }
}

// ------------------------------- main kernel -------------------------------
__global__ void __launch_bounds__(THREADS, 3)
kpconv_mma(const float* __restrict__ features,
           const float* __restrict__ outpts,
           const int*   __restrict__ nbr,
           const float* __restrict__ kpts,
           float*       __restrict__ out)
{
    extern __shared__ char smem[];
    const uint32_t smem_base = smem_u32(smem);
    float*    s_kp = reinterpret_cast<float*>(smem + S_KP);
    unsigned* s_km = reinterpret_cast<unsigned*>(smem + S_KM);
    float4*   s_pq = reinterpret_cast<float4*>(smem + S_PQ);

    const int tid = threadIdx.x;
    const int wid = tid >> 5;
    const int ln  = tid & 31;
    const int m0  = blockIdx.x * MT;

    if (tid < KP * 3) s_kp[(tid / 3) * 4 + (tid % 3)] = kpts[tid];
    __syncthreads();

    // ---- setup: pq vectors + per-(m,k) neighbor bitmasks ----
    #pragma unroll 1
    for (int j = 0; j < (MT * NNB) / THREADS; ++j) {
        const int i = j * THREADS + tid;
        const int m = i >> 5;                 // constant within a warp
        const int gm = m0 + m;
        float dx, dy, dz;
        int gi = 0;
        if (gm < Mpts) {
            gi = nbr[(size_t)gm * NNB + ln];
            const float4 pp = __ldg(g_pts + gi);       // one aligned LDG.128
            dx = pp.x - outpts[gm * 3 + 0];
            dy = pp.y - outpts[gm * 3 + 1];
            dz = pp.z - outpts[gm * 3 + 2];
        } else {
            dx = dy = dz = 1e18f;
        }
        s_pq[i] = make_float4(dx, dy, dz, __int_as_float(gi));
        #pragma unroll
        for (int k = 0; k < KP; ++k) {
            const float ex = dx - s_kp[k * 4 + 0];
            const float ey = dy - s_kp[k * 4 + 1];
            const float ez = dz - s_kp[k * 4 + 2];
            const float d2 = ex * ex + ey * ey + ez * ez;
            const unsigned bal = __ballot_sync(0xffffffffu, d2 < 1.0f);
            if (ln == 0) s_km[m * 16 + k] = bal;
        }
    }

    // ---- per-thread mappings ----
    const int mgrp = tid >> 3;          // gather: 8 threads per m, 32 m's per pass
    const int oct  = tid & 7;           // 16B chunk index: oct and oct+8

    const int wm = (wid & 3) * 16;      // mma warp tile: rows
    const int wc = (wid >> 2) * 32;     // mma warp tile: cols
    const uint32_t aaddr = smem_base + A_T0 +
        (uint32_t)((wm + (ln & 7) + ((ln >> 3) & 1) * 8) * TSTR_B + ((ln >> 4) & 1) * 16);
    const uint4* bwarp = g_Bfrag + ((wid >> 2) * 8 * 2) * 32 + ln;

    float Dacc[4][4];
    #pragma unroll
    for (int a = 0; a < 4; ++a)
        #pragma unroll
        for (int b = 0; b < 4; ++b) Dacc[a][b] = 0.f;

    __syncthreads();   // masks + pq visible

    #pragma unroll 1
    for (int k = 0; k < KP; ++k) {
        const float kpx = s_kp[k * 4 + 0];
        const float kpy = s_kp[k * 4 + 1];
        const float kpz = s_kp[k * 4 + 2];

        // ---------- gather wf_k: 8 threads/m, fully coalesced rows ----------
        float acc[2][8];
        #pragma unroll
        for (int p = 0; p < 2; ++p)
            #pragma unroll
            for (int i = 0; i < 8; ++i) acc[p][i] = 0.f;

        #pragma unroll
        for (int p = 0; p < 2; ++p) {
            const int m = p * 32 + mgrp;
            unsigned mask = s_km[m * 16 + k];
            const float4* pqm = s_pq + m * 32;
            while (mask) {
                const int n0 = __ffs(mask) - 1;
                mask &= mask - 1;
                const bool has1 = (mask != 0);
                int n1 = n0;
                if (has1) { n1 = __ffs(mask) - 1; mask &= mask - 1; }

                const float4 pq0 = pqm[n0];       // broadcast LDS across octs
                const float4 pq1 = pqm[n1];

                const float4* fp0 = reinterpret_cast<const float4*>(
                    features + (size_t)__float_as_int(pq0.w) * FD);
                const float4* fp1 = reinterpret_cast<const float4*>(
                    features + (size_t)__float_as_int(pq1.w) * FD);
                const float4 a0 = __ldg(fp0 + oct);
                const float4 b0 = __ldg(fp0 + oct + 8);
                const float4 a1 = __ldg(fp1 + oct);
                const float4 b1 = __ldg(fp1 + oct + 8);

                const float ex0 = pq0.x - kpx, ey0 = pq0.y - kpy, ez0 = pq0.z - kpz;
                const float w0 = 1.0f - __fsqrt_rn(ex0 * ex0 + ey0 * ey0 + ez0 * ez0);
                float w1 = 0.0f;
                if (has1) {
                    const float ex1 = pq1.x - kpx, ey1 = pq1.y - kpy, ez1 = pq1.z - kpz;
                    w1 = 1.0f - __fsqrt_rn(ex1 * ex1 + ey1 * ey1 + ez1 * ez1);
                }
                acc[p][0] += w0 * a0.x + w1 * a1.x;
                acc[p][1] += w0 * a0.y + w1 * a1.y;
                acc[p][2] += w0 * a0.z + w1 * a1.z;
                acc[p][3] += w0 * a0.w + w1 * a1.w;
                acc[p][4] += w0 * b0.x + w1 * b1.x;
                acc[p][5] += w0 * b0.y + w1 * b1.y;
                acc[p][6] += w0 * b0.z + w1 * b1.z;
                acc[p][7] += w0 * b0.w + w1 * b1.w;
            }
        }

        // ---------- tf32-round + STS A tile into parity buffer ----------
        const uint32_t abase = (uint32_t)((k & 1) * ATILE_BYTES);
        #pragma unroll
        for (int p = 0; p < 2; ++p) {
            const int m = p * 32 + mgrp;
            uint32_t t[8];
            #pragma unroll
            for (int i = 0; i < 8; ++i) t[i] = tf32r(acc[p][i]);
            const uint32_t base = abase + (uint32_t)(m * TSTR_B + oct * 16);
            *reinterpret_cast<uint4*>(smem + base)       = make_uint4(t[0], t[1], t[2], t[3]);
            *reinterpret_cast<uint4*>(smem + base + 128) = make_uint4(t[4], t[5], t[6], t[7]);
        }
        __syncthreads();   // A(k) visible; MMA(k-1) ldmatrix already issued by all warps

        // ---------- mma: D += A · B  (tf32; B operands via coalesced LDG) ----------
        const uint4* bk = bwarp + (size_t)k * (2 * 8 * 2 * 32);
        const uint32_t abuf = aaddr + abase;
        #pragma unroll
        for (int ks = 0; ks < 8; ++ks) {
            uint32_t a[4];
            ldmx4(a, abuf + ks * 32);
            #pragma unroll
            for (int nt2 = 0; nt2 < 2; ++nt2) {
                const uint4 bb = __ldg(bk + (ks * 2 + nt2) * 32);
                mma1688(Dacc[nt2 * 2 + 0], a, bb.x, bb.y);
                mma1688(Dacc[nt2 * 2 + 1], a, bb.z, bb.w);
            }
        }
    }

    // ---------- epilogue ----------
    const int gid = ln >> 2, tg = ln & 3;
    const int r0 = m0 + wm + gid;
    const int r1 = r0 + 8;
    #pragma unroll
    for (int nt = 0; nt < 4; ++nt) {
        const int cc = wc + nt * 8 + tg * 2;
        if (r0 < Mpts)
            *reinterpret_cast<float2*>(out + (size_t)r0 * CD + cc) =
                make_float2(Dacc[nt][0], Dacc[nt][1]);
        if (r1 < Mpts)
            *reinterpret_cast<float2*>(out + (size_t)r1 * CD + cc) =
                make_float2(Dacc[nt][2], Dacc[nt][3]);
    }
}

extern "C" void kernel_launch(void* const* d_in, const int* in_sizes, int n_in,
                              void* d_out, int out_size)
{
    const float* points   = (const float*)d_in[0];
    const float* features = (const float*)d_in[1];
    const float* outpts   = (const float*)d_in[2];
    const int*   nbr      = (const int*)  d_in[3];
    const float* kpts     = (const float*)d_in[4];
    const float* kvals    = (const float*)d_in[5];

    pts_prep<<<(Npts + 255) / 256, 256>>>(points);
    bfrag_prep<<<KP, 64>>>(kvals);

    cudaFuncSetAttribute(kpconv_mma, cudaFuncAttributeMaxDynamicSharedMemorySize, SMEM_TOTAL);
    kpconv_mma<<<GRID, THREADS, SMEM_TOTAL>>>(features, outpts, nbr, kpts, (float*)d_out);
}